// round 11
// baseline (speedup 1.0000x reference)
#include <cuda_runtime.h>

// Problem constants (from reference)
#define KORD 8
#define NUMI 15
#define GBAS (NUMI + KORD)        // 23 basis functions
#define BB 1024
#define NN 34
#define HH 256
#define WW 256
#define IMG_FLOATS (2 * HH * WW)  // 131072 floats per image
#define CH_STRIDE (HH * WW)

#define GRID 512
#define BLOCK 256
#define IMG_PER_BLK (BB / GRID)   // 2 images per block
#define TOTAL_F4 (BB * IMG_FLOATS / 4)  // 33554432 float4

// Re-entrant grid-barrier ticket counter. Monotonic across graph replays:
// each replay's arrivals push it up by GRID; waiters compute their own
// target from their ticket, so no reset is ever needed.
__device__ unsigned long long g_bar = 0ULL;

// Order-8 B-spline KAN edge via local de Boor: only the K+1=9 basis functions
// covering x are nonzero. Uniform knots (h = 4/15) make every denominator in
// the triangular recurrence a compile-time constant -> pure FFMA, 9 registers.
// Out-of-range x: all reference indicators are zero -> only base*silu survives.
// coef/base point to SHARED memory (staged tables).
__device__ __forceinline__ float spline_apply_one(float x, int id,
                                                  const float* coef,
                                                  const float* base) {
    float res = base[id] * __fdividef(x, 1.0f + __expf(-x));  // base * silu

    const float invh = 15.0f / 4.0f;
    const float g0   = -2.0f - (float)KORD * (4.0f / 15.0f);  // grid[0]

    float u = (x - g0) * invh;                        // position in knot units
    float mf = floorf(u);
    int m = (int)mf;
    if (m < 0 || m > 30) return res;                  // outside knot range
    float t = u - mf;                                 // local coord in [0,1)

    // de Boor: N[r] = B_{m-8+r}(x) after the last iteration
    float N[KORD + 1];
    N[0] = 1.0f;
#pragma unroll
    for (int j = 1; j <= KORD; j++) {
        const float invj = 1.0f / (float)j;           // compile-time constant
        float saved = 0.0f;
#pragma unroll
        for (int r = 0; r < j; r++) {
            float temp = N[r] * invj;
            N[r] = saved + ((float)(r + 1) - t) * temp;
            saved = (t + (float)(j - 1 - r)) * temp;
        }
        N[j] = saved;
    }

    const float* crow = coef + id * GBAS;
#pragma unroll
    for (int r = 0; r <= KORD; r++) {
        int jdx = m - KORD + r;
        if (jdx >= 0 && jdx < GBAS)
            res += crow[jdx] * N[r];
    }
    return res;
}

// Single persistent kernel, 512 blocks x 256 threads, all co-resident
// (launch_bounds(256,4): 4*148 = 592 >= 512 -> the grid barrier is safe).
// Phase 0: stage this block's 2 xv rows + all spline tables into smem.
// Phase 1: uniform grid-stride zero of the full 512 MB output.
// Grid barrier (release/acquire via threadfence + ticket counter).
// Phase 2: scatter the 2 owned images from smem-resident data.
__global__ void __launch_bounds__(BLOCK, 4)
vec2im_kernel(const float* __restrict__ xv,
              const float* __restrict__ dcoef,
              const float* __restrict__ dbase,
              const float* __restrict__ ccoef,
              const float* __restrict__ cbase,
              float* __restrict__ out) {
    __shared__ float s_xv[IMG_PER_BLK * NN * 5];   // 340 floats
    __shared__ float s_dc[34 * GBAS];              // 782 floats
    __shared__ float s_db[34];
    __shared__ float s_cc[5 * GBAS];               // 115 floats
    __shared__ float s_cb[5];
    __shared__ int   s_cx[IMG_PER_BLK][NN];
    __shared__ int   s_cy[IMG_PER_BLK][NN];

    const int tid = threadIdx.x;
    const int b0 = blockIdx.x * IMG_PER_BLK;

    // ---- Phase 0: stage inputs (independent of the zero stores) ----
    const float* vb = xv + (size_t)b0 * NN * 5;
#pragma unroll
    for (int i = tid; i < IMG_PER_BLK * NN * 5; i += BLOCK) s_xv[i] = vb[i];
#pragma unroll
    for (int i = tid; i < 34 * GBAS; i += BLOCK) s_dc[i] = dcoef[i];
    if (tid < 34) s_db[tid] = dbase[tid];
    else if (tid >= 64 && tid < 64 + 5 * GBAS) s_cc[tid - 64] = ccoef[tid - 64];
    else if (tid >= 192 && tid < 197) s_cb[tid - 192] = cbase[tid - 192];

    // ---- Phase 1: grid-stride zero of the whole output ----
    {
        float4* o4 = (float4*)out;
        const float4 z = make_float4(0.f, 0.f, 0.f, 0.f);
        const int stride = GRID * BLOCK;             // 131072
#pragma unroll 8
        for (int i = blockIdx.x * BLOCK + tid; i < TOTAL_F4; i += stride)
            o4[i] = z;
    }

    // ---- Grid barrier (re-entrant ticket) ----
    __syncthreads();                 // all block stores issued
    __shared__ unsigned long long s_ticket;
    if (tid == 0) {
        __threadfence();             // release: zeros visible before arrival
        s_ticket = atomicAdd(&g_bar, 1ULL);
    }
    __syncthreads();
    if (tid == 0) {
        unsigned long long target = (s_ticket / GRID + 1ULL) * GRID;
        while (atomicAdd(&g_bar, 0ULL) < target) { }
        __threadfence();             // acquire: all blocks' zeros visible
    }
    __syncthreads();

    // ---- Phase 2: scatter the block's 2 images ----
    const int sub = tid >> 7;        // 0..1 (128 threads per image)
    const int n = tid & 127;         // point index within image
    const float* sv = s_xv + sub * NN * 5;

    int cx = 0, cy = 0;
    if (n < NN) {
        cx = (int)rintf(sv[n * 5 + 1]);
        cy = (int)rintf(sv[n * 5 + 2]);
        s_cx[sub][n] = cx;
        s_cy[sub][n] = cy;
    }
    __syncthreads();

    if (n >= NN) return;

    float power = sv[n * 5 + 0];
    int dev = (int)sv[n * 5 + 3];
    int cat = (int)sv[n * 5 + 4];

    // Last-write-wins in index order: dead if any LATER point collides.
    bool dead = false;
#pragma unroll 4
    for (int m = n + 1; m < NN; m++)
        dead |= (s_cx[sub][m] == cx) & (s_cy[sub][m] == cy);
    if (dead) return;

    float p = spline_apply_one(power, dev, s_dc, s_db);
    p       = spline_apply_one(p,     cat, s_cc, s_cb);

    size_t base_off = (size_t)(b0 + sub) * IMG_FLOATS;
    size_t pix = (size_t)cy * WW + cx;
    out[base_off + pix] = p;                  // channel 0
    out[base_off + CH_STRIDE + pix] = power;  // channel 1
}

extern "C" void kernel_launch(void* const* d_in, const int* in_sizes, int n_in,
                              void* d_out, int out_size) {
    const float* xv    = (const float*)d_in[0]; // (1024,34,5)
    const float* dcoef = (const float*)d_in[1]; // (34,23)
    const float* dbase = (const float*)d_in[2]; // (34,)
    const float* ccoef = (const float*)d_in[3]; // (5,23)
    const float* cbase = (const float*)d_in[4]; // (5,)
    float* out = (float*)d_out;                 // (1024,2,256,256)

    vec2im_kernel<<<GRID, BLOCK>>>(xv, dcoef, dbase, ccoef, cbase, out);
}

// round 12
// speedup vs baseline: 1.2190x; 1.2190x over previous
#include <cuda_runtime.h>

// Problem constants (from reference)
#define KORD 8
#define NUMI 15
#define GBAS (NUMI + KORD)        // 23 basis functions
#define BB 1024
#define NN 34
#define HH 256
#define WW 256
#define IMG_FLOATS (2 * HH * WW)  // 131072 floats per image
#define CH_STRIDE (HH * WW)
#define IMG_PER_BLK 4
#define NBLK (BB / IMG_PER_BLK)   // 256 blocks

// Order-8 B-spline KAN edge via local de Boor: only the K+1=9 basis functions
// covering x are nonzero. Uniform knots (h = 4/15) make every denominator in
// the triangular recurrence a compile-time constant -> pure FFMA, 9 registers.
// Out-of-range x: all reference indicators are zero -> only base*silu survives.
// coef/base point to SHARED memory (staged tables).
__device__ __forceinline__ float spline_apply_one(float x, int id,
                                                  const float* coef,
                                                  const float* base) {
    float res = base[id] * __fdividef(x, 1.0f + __expf(-x));  // base * silu

    const float invh = 15.0f / 4.0f;
    const float g0   = -2.0f - (float)KORD * (4.0f / 15.0f);  // grid[0]

    float u = (x - g0) * invh;                        // position in knot units
    float mf = floorf(u);
    int m = (int)mf;
    if (m < 0 || m > 30) return res;                  // outside knot range
    float t = u - mf;                                 // local coord in [0,1)

    // de Boor: N[r] = B_{m-8+r}(x) after the last iteration
    float N[KORD + 1];
    N[0] = 1.0f;
#pragma unroll
    for (int j = 1; j <= KORD; j++) {
        const float invj = 1.0f / (float)j;           // compile-time constant
        float saved = 0.0f;
#pragma unroll
        for (int r = 0; r < j; r++) {
            float temp = N[r] * invj;
            N[r] = saved + ((float)(r + 1) - t) * temp;
            saved = (t + (float)(j - 1 - r)) * temp;
        }
        N[j] = saved;
    }

    const float* crow = coef + id * GBAS;
#pragma unroll
    for (int r = 0; r <= KORD; r++) {
        int jdx = m - KORD + r;
        if (jdx >= 0 && jdx < GBAS)
            res += crow[jdx] * N[r];
    }
    return res;
}

// 4 images per 256-thread block (256 blocks). Each 64-thread group owns one
// image; thread n<34 loads its point's 5 floats directly (each image row is
// 6 cache lines, shared by the whole group). Rounded coords go to smem;
// ONE sync covers coords + spline-table staging. Channel-1 store (raw power,
// no spline needed) issues immediately after the collision check so its
// write latency drains under the two spline evaluations.
__global__ void __launch_bounds__(256)
scatter_kernel(const float* __restrict__ xv,
               const float* __restrict__ dcoef,
               const float* __restrict__ dbase,
               const float* __restrict__ ccoef,
               const float* __restrict__ cbase,
               float* __restrict__ out) {
    __shared__ float s_dc[34 * GBAS];              // 782 floats
    __shared__ float s_db[34];
    __shared__ float s_cc[5 * GBAS];               // 115 floats
    __shared__ float s_cb[5];
    __shared__ int   s_cx[IMG_PER_BLK][NN];
    __shared__ int   s_cy[IMG_PER_BLK][NN];

    const int tid = threadIdx.x;
    const int sub = tid >> 6;          // image within block (0..3)
    const int n = tid & 63;            // point within image
    const int b = blockIdx.x * IMG_PER_BLK + sub;

    // Per-point direct loads (issued first: longest-latency chain head)
    float power = 0.f; int cx = 0, cy = 0, dev = 0, cat = 0;
    if (n < NN) {
        const float* v = xv + ((size_t)b * NN + n) * 5;
        power = v[0];
        cx = (int)rintf(v[1]);
        cy = (int)rintf(v[2]);
        dev = (int)v[3];
        cat = (int)v[4];
        s_cx[sub][n] = cx;
        s_cy[sub][n] = cy;
    }

    // Table staging (independent loads, overlap the xv latency)
#pragma unroll
    for (int i = tid; i < 34 * GBAS; i += 256) s_dc[i] = dcoef[i];
    if (tid < 34) s_db[tid] = dbase[tid];
    else if (tid >= 64 && tid < 64 + 5 * GBAS) s_cc[tid - 64] = ccoef[tid - 64];
    else if (tid >= 192 && tid < 197) s_cb[tid - 192] = cbase[tid - 192];

    __syncthreads();                   // coords + tables visible

    if (n >= NN) return;

    // Last-write-wins in index order: dead if any LATER point collides.
    bool dead = false;
#pragma unroll 4
    for (int m = n + 1; m < NN; m++)
        dead |= (s_cx[sub][m] == cx) & (s_cy[sub][m] == cy);
    if (dead) return;

    const size_t base_off = (size_t)b * IMG_FLOATS;
    const size_t pix = (size_t)cy * WW + cx;

    // Channel 1 store first — needs no spline, drains under the compute.
    out[base_off + CH_STRIDE + pix] = power;

    float p = spline_apply_one(power, dev, s_dc, s_db);
    p       = spline_apply_one(p,     cat, s_cc, s_cb);

    out[base_off + pix] = p;           // channel 0
}

extern "C" void kernel_launch(void* const* d_in, const int* in_sizes, int n_in,
                              void* d_out, int out_size) {
    const float* xv    = (const float*)d_in[0]; // (1024,34,5)
    const float* dcoef = (const float*)d_in[1]; // (34,23)
    const float* dbase = (const float*)d_in[2]; // (34,)
    const float* ccoef = (const float*)d_in[3]; // (5,23)
    const float* cbase = (const float*)d_in[4]; // (5,)
    float* out = (float*)d_out;                 // (1024,2,256,256)

    // Phase 1: single driver bulk zero-fill (~7.2 TB/s, at the write
    // roofline — measured faster than any SM-kernel store loop on this part).
    cudaMemsetAsync(out, 0, (size_t)out_size * sizeof(float), 0);

    // Phase 2: sparse scatter, 4 images per block.
    scatter_kernel<<<NBLK, 256>>>(xv, dcoef, dbase, ccoef, cbase, out);
}